// round 1
// baseline (speedup 1.0000x reference)
#include <cuda_runtime.h>
#include <cstdint>

#define NN 100000
#define EE 1600000
#define HID 128
#define INDIM 16
#define LN_EPS 1e-5f

// ------------------------- device scratch (no allocs allowed) ---------------
__device__ int   g_deg[NN];
__device__ int   g_cursor[NN];
__device__ int   g_rowptr[NN + 1];
__device__ int   g_esrc[EE];
__device__ float g_ecoef[EE];
__device__ float g_dis[NN];
__device__ float g_h0[NN * HID];
__device__ float g_h1[NN * HID];
__device__ float g_agg[NN * HID];

// ------------------------- f32x2 helpers ------------------------------------
__device__ __forceinline__ unsigned long long pk2(float x, float y) {
    unsigned long long r;
    asm("mov.b64 %0, {%1, %2};" : "=l"(r) : "f"(x), "f"(y));
    return r;
}
__device__ __forceinline__ unsigned long long ffma2(unsigned long long a,
                                                    unsigned long long b,
                                                    unsigned long long c) {
    unsigned long long d;
    asm("fma.rn.f32x2 %0, %1, %2, %3;" : "=l"(d) : "l"(a), "l"(b), "l"(c));
    return d;
}
__device__ __forceinline__ float2 upk2(unsigned long long a) {
    float2 f;
    asm("mov.b64 {%0, %1}, %2;" : "=f"(f.x), "=f"(f.y) : "l"(a));
    return f;
}

// ------------------------- graph preprocessing -------------------------------
__global__ void count_deg_k(const int* __restrict__ ei) {
    int e = blockIdx.x * blockDim.x + threadIdx.x;
    if (e < EE) atomicAdd(&g_deg[ei[EE + e]], 1);
}

__global__ void dis_k() {
    int n = blockIdx.x * blockDim.x + threadIdx.x;
    if (n < NN) g_dis[n] = rsqrtf((float)(g_deg[n] + 1));  // +1 self loop
}

// exclusive scan of g_deg -> g_rowptr, single block of 1024
__global__ void scan_k() {
    __shared__ int ssum[1024];
    int t = threadIdx.x;
    const int per = (NN + 1023) / 1024;  // 98
    int start = t * per;
    int end = start + per;
    if (start > NN) start = NN;
    if (end > NN) end = NN;
    int s = 0;
    for (int i = start; i < end; i++) s += g_deg[i];
    ssum[t] = s;
    __syncthreads();
    for (int d = 1; d < 1024; d <<= 1) {
        int v = (t >= d) ? ssum[t - d] : 0;
        __syncthreads();
        ssum[t] += v;
        __syncthreads();
    }
    int off = ssum[t] - s;  // exclusive prefix of this chunk
    for (int i = start; i < end; i++) { g_rowptr[i] = off; off += g_deg[i]; }
    if (t == 1023) g_rowptr[NN] = off;
}

__global__ void build_csr_k(const int* __restrict__ ei) {
    int e = blockIdx.x * blockDim.x + threadIdx.x;
    if (e >= EE) return;
    int s = ei[e];
    int d = ei[EE + e];
    int pos = g_rowptr[d] + atomicAdd(&g_cursor[d], 1);
    g_esrc[pos]  = s;
    g_ecoef[pos] = g_dis[s] * g_dis[d];
}

// ------------------------- input projection: h0 = x @ W_in + b_in -----------
__global__ void in_proj_k(const float* __restrict__ x,
                          const float* __restrict__ Win,
                          const float* __restrict__ bin) {
    __shared__ float sW[INDIM * HID];
    int tid = threadIdx.x;
    for (int i = tid; i < INDIM * HID / 4; i += blockDim.x)
        ((float4*)sW)[i] = ((const float4*)Win)[i];
    __syncthreads();
    int gidx = blockIdx.x * blockDim.x + tid;
    int row  = gidx >> 5;
    int lane = gidx & 31;
    if (row >= NN) return;
    int c0 = lane * 4;
    float4 b = ((const float4*)bin)[lane];
    float a0 = b.x, a1 = b.y, a2 = b.z, a3 = b.w;
    const float* xr = x + row * INDIM;
#pragma unroll
    for (int k = 0; k < INDIM; k++) {
        float xv = __ldg(xr + k);
        float4 w = *(const float4*)&sW[k * HID + c0];
        a0 += xv * w.x; a1 += xv * w.y; a2 += xv * w.z; a3 += xv * w.w;
    }
    float4 o = make_float4(a0, a1, a2, a3);
    *(float4*)&g_h0[row * HID + c0] = o;
}

// ------------------------- per-layer aggregation (CSR gather) ----------------
// agg[n] = dis[n]^2*h[n] + sum_e coef_e * h[src_e],  warp per node, float4/lane
__global__ void aggregate_k(const float* __restrict__ h) {
    int n    = (blockIdx.x * blockDim.x + threadIdx.x) >> 5;
    int lane = threadIdx.x & 31;
    if (n >= NN) return;
    const float4* hp = (const float4*)h;
    float dn = g_dis[n];
    float sl = dn * dn;
    float4 hv = hp[n * 32 + lane];
    float4 a0 = make_float4(sl * hv.x, sl * hv.y, sl * hv.z, sl * hv.w);
    float4 a1 = make_float4(0.f, 0.f, 0.f, 0.f);
    int j = g_rowptr[n], end = g_rowptr[n + 1];
    for (; j + 1 < end; j += 2) {
        int s0 = g_esrc[j], s1 = g_esrc[j + 1];
        float c0 = g_ecoef[j], c1 = g_ecoef[j + 1];
        float4 v0 = hp[s0 * 32 + lane];
        float4 v1 = hp[s1 * 32 + lane];
        a0.x += c0 * v0.x; a0.y += c0 * v0.y; a0.z += c0 * v0.z; a0.w += c0 * v0.w;
        a1.x += c1 * v1.x; a1.y += c1 * v1.y; a1.z += c1 * v1.z; a1.w += c1 * v1.w;
    }
    if (j < end) {
        int s0 = g_esrc[j];
        float c0 = g_ecoef[j];
        float4 v0 = hp[s0 * 32 + lane];
        a0.x += c0 * v0.x; a0.y += c0 * v0.y; a0.z += c0 * v0.z; a0.w += c0 * v0.w;
    }
    float4 o = make_float4(a0.x + a1.x, a0.y + a1.y, a0.z + a1.z, a0.w + a1.w);
    ((float4*)g_agg)[n * 32 + lane] = o;
}

// ------------------------- fused GEMM + bias + LN + ReLU + residual ----------
// out[rows 64/block] = relu(LN(agg @ W + b)) [+ hprev]
// 8 warps/block, 8 rows/warp, 4 cols/lane, packed f32x2 FMAs.
__global__ __launch_bounds__(256, 2) void gemm_ln_k(
    const float* __restrict__ Wc, const float* __restrict__ bc,
    const float* __restrict__ gamma, const float* __restrict__ beta,
    const float* __restrict__ hprev, float* __restrict__ out, int do_res) {
    extern __shared__ float smem[];
    float* sW = smem;          // 128*128 = 16384 floats
    float* sA = smem + 16384;  // 64*128  =  8192 floats
    int tid  = threadIdx.x;
    int row0 = blockIdx.x * 64;

    for (int i = tid; i < 4096; i += 256)
        ((float4*)sW)[i] = ((const float4*)Wc)[i];
    {
        const float4* Ag = (const float4*)g_agg;
        int base = row0 * 32;
        for (int i = tid; i < 2048; i += 256) {
            int gi = base + i;
            float4 v = (gi < NN * 32) ? Ag[gi] : make_float4(0.f, 0.f, 0.f, 0.f);
            ((float4*)sA)[i] = v;
        }
    }
    __syncthreads();

    int warp = tid >> 5, lane = tid & 31;
    int rbase = warp * 8;
    int c0 = lane * 4;
    unsigned long long acc[8][2];
#pragma unroll
    for (int r = 0; r < 8; r++) { acc[r][0] = 0ull; acc[r][1] = 0ull; }

    for (int k = 0; k < 128; k++) {
        float4 w = *(const float4*)&sW[k * 128 + c0];
        unsigned long long w01 = pk2(w.x, w.y);
        unsigned long long w23 = pk2(w.z, w.w);
#pragma unroll
        for (int r = 0; r < 8; r++) {
            float a = sA[(rbase + r) * 128 + k];
            unsigned long long aa = pk2(a, a);
            acc[r][0] = ffma2(aa, w01, acc[r][0]);
            acc[r][1] = ffma2(aa, w23, acc[r][1]);
        }
    }

    float4 bv  = ((const float4*)bc)[lane];
    float4 gv  = ((const float4*)gamma)[lane];
    float4 btv = ((const float4*)beta)[lane];

#pragma unroll
    for (int r = 0; r < 8; r++) {
        int row = row0 + rbase + r;          // uniform across warp
        if (row >= NN) continue;
        float2 p0 = upk2(acc[r][0]);
        float2 p1 = upk2(acc[r][1]);
        float o0 = p0.x + bv.x, o1 = p0.y + bv.y;
        float o2 = p1.x + bv.z, o3 = p1.y + bv.w;
        float s = o0 + o1 + o2 + o3;
#pragma unroll
        for (int d = 16; d; d >>= 1) s += __shfl_xor_sync(0xffffffffu, s, d);
        float mean = s * (1.0f / 128.0f);
        float d0 = o0 - mean, d1 = o1 - mean, d2 = o2 - mean, d3 = o3 - mean;
        float q = d0 * d0 + d1 * d1 + d2 * d2 + d3 * d3;
#pragma unroll
        for (int d = 16; d; d >>= 1) q += __shfl_xor_sync(0xffffffffu, q, d);
        float rinv = rsqrtf(q * (1.0f / 128.0f) + LN_EPS);
        float v0 = fmaxf(d0 * rinv * gv.x + btv.x, 0.f);
        float v1 = fmaxf(d1 * rinv * gv.y + btv.y, 0.f);
        float v2 = fmaxf(d2 * rinv * gv.z + btv.z, 0.f);
        float v3 = fmaxf(d3 * rinv * gv.w + btv.w, 0.f);
        if (do_res) {
            float4 hp = ((const float4*)hprev)[row * 32 + lane];
            v0 += hp.x; v1 += hp.y; v2 += hp.z; v3 += hp.w;
        }
        float4 o = make_float4(v0, v1, v2, v3);
        ((float4*)out)[row * 32 + lane] = o;
    }
}

// ------------------------- host launch ---------------------------------------
extern "C" void kernel_launch(void* const* d_in, const int* in_sizes, int n_in,
                              void* d_out, int out_size) {
    const float* x     = (const float*)d_in[0];
    const int*   ei    = (const int*)d_in[1];   // jax default: int32
    const float* Win   = (const float*)d_in[2];
    const float* bin   = (const float*)d_in[3];
    const float* Wconv = (const float*)d_in[4];
    const float* bconv = (const float*)d_in[5];
    const float* gamma = (const float*)d_in[6];
    const float* beta  = (const float*)d_in[7];
    float* out = (float*)d_out;

    (void)in_sizes; (void)n_in; (void)out_size;

    cudaFuncSetAttribute(gemm_ln_k, cudaFuncAttributeMaxDynamicSharedMemorySize,
                         (16384 + 8192) * (int)sizeof(float));

    void *degp, *curp, *h0p, *h1p;
    cudaGetSymbolAddress(&degp, g_deg);
    cudaGetSymbolAddress(&curp, g_cursor);
    cudaGetSymbolAddress(&h0p, g_h0);
    cudaGetSymbolAddress(&h1p, g_h1);
    float* hbuf[2] = {(float*)h0p, (float*)h1p};

    cudaMemsetAsync(degp, 0, NN * sizeof(int));
    cudaMemsetAsync(curp, 0, NN * sizeof(int));

    count_deg_k<<<(EE + 255) / 256, 256>>>(ei);
    dis_k<<<(NN + 255) / 256, 256>>>();
    scan_k<<<1, 1024>>>();
    build_csr_k<<<(EE + 255) / 256, 256>>>(ei);
    in_proj_k<<<(NN * 32 + 255) / 256, 256>>>(x, Win, bin);

    int p = 0;
    for (int l = 0; l < 3; l++) {
        aggregate_k<<<(NN * 32 + 255) / 256, 256>>>(hbuf[p]);
        float* dst = (l == 2) ? out : hbuf[1 - p];
        gemm_ln_k<<<(NN + 63) / 64, 256, (16384 + 8192) * sizeof(float)>>>(
            Wconv + (size_t)l * HID * HID, bconv + l * HID,
            gamma + l * HID, beta + l * HID, hbuf[p], dst, l > 0);
        p ^= 1;
    }
}